// round 15
// baseline (speedup 1.0000x reference)
#include <cuda_runtime.h>
#include <cuda_bf16.h>
#include <math.h>

#define SQ 4096
#define DD 1024
#define HH 512
#define TT 20
#define G4H 2048
#define NEGV -10000.0f

// ---------------- static scratch (allocation-free) ----------------
__device__ float g_pre[2][SQ][G4H];     // input projections + bias
__device__ float g_hout[2][SQ][HH];     // hidden states, natural position order
__device__ uint4 g_hp[2][2][HH / 2];    // [parity][dir][e]: {h(2e),tag, h(2e+1),tag}
__device__ int   g_pre_ready[2][32];    // per (dir, m-block) completed n-block count
__device__ float g_feats[SQ][TT];       // emission scores

__device__ __forceinline__ int ld_acq(const int* p) {
    int v; asm volatile("ld.acquire.gpu.global.b32 %0, [%1];" : "=r"(v) : "l"(p)); return v;
}

// fast activations: ex2.approx-based, ~1e-6 rel error, clamped (no inf/inf)
__device__ __forceinline__ float fast_sig(float x) {
    float e = __expf(-x);
    return __fdividef(1.f, 1.f + e);
}
__device__ __forceinline__ float fast_tanh(float x) {
    float xc = fminf(fmaxf(x, -15.f), 15.f);
    float e = __expf(2.f * xc);
    return __fdividef(e - 1.f, e + 1.f);
}

// bf16 split helpers: f = hi + lo with |dropped| ~ 2^-16 relative
__device__ __forceinline__ void cvt2(float f0, float f1, unsigned& uh, unsigned& ul) {
    __nv_bfloat16 h0 = __float2bfloat16(f0), h1 = __float2bfloat16(f1);
    float r0 = f0 - __bfloat162float(h0);
    float r1 = f1 - __bfloat162float(h1);
    __nv_bfloat16 l0 = __float2bfloat16(r0), l1 = __float2bfloat16(r1);
    uh = (unsigned)__bfloat16_as_ushort(h0) | ((unsigned)__bfloat16_as_ushort(h1) << 16);
    ul = (unsigned)__bfloat16_as_ushort(l0) | ((unsigned)__bfloat16_as_ushort(l1) << 16);
}

__device__ __forceinline__ void ldm_x4(unsigned& r0, unsigned& r1, unsigned& r2, unsigned& r3,
                                       unsigned addr) {
    asm volatile("ldmatrix.sync.aligned.m8n8.x4.shared.b16 {%0,%1,%2,%3}, [%4];"
                 : "=r"(r0), "=r"(r1), "=r"(r2), "=r"(r3) : "r"(addr));
}

#define MMA16816(c, a, b0, b1)                                              \
    asm volatile("mma.sync.aligned.m16n8k16.row.col.f32.bf16.bf16.f32 "     \
        "{%0,%1,%2,%3}, {%4,%5,%6,%7}, {%8,%9}, {%0,%1,%2,%3};"             \
        : "+f"((c)[0]), "+f"((c)[1]), "+f"((c)[2]), "+f"((c)[3])            \
        : "r"((a)[0]), "r"((a)[1]), "r"((a)[2]), "r"((a)[3]),               \
          "r"(b0), "r"(b1))

// ---------------- kernel 0: per-replay init ----------------
__global__ void init_kernel(const float* __restrict__ h0) {
    int t = threadIdx.x;                 // 1024 threads
    int dir = t >> 9, k = t & (HH - 1);
    uint2* even = (uint2*)&g_hp[0][dir][0];
    uint2* odd  = (uint2*)&g_hp[1][dir][0];
    even[k] = make_uint2(__float_as_uint(h0[dir * HH + k]), 0u);   // h_0, tag 0
    odd[k]  = make_uint2(0u, 0xFFFFFFFFu);                         // poison
    if (t < 64) ((int*)g_pre_ready)[t] = 0;
}

__global__ void dummy_kernel() {}

// ---------------- kernel 1: gather + input projection, tensor-core bf16-split ----------------
// D = Ah*Bh + Ah*Bl + Al*Bh (3-term double-bf16, fp32 accum), ~1e-5 relative error.
__global__ __launch_bounds__(256) void gemm_pre_kernel(
    const int* __restrict__ sent, const float* __restrict__ embed,
    const float* __restrict__ Wf, const float* __restrict__ bf,
    const float* __restrict__ Wb, const float* __restrict__ bb)
{
    const int dir   = blockIdx.x;
    const int mprio = blockIdx.z;
    const int mblk  = dir ? (31 - mprio) : mprio;
    const float* __restrict__ W    = dir ? Wb : Wf;
    const float* __restrict__ bias = dir ? bb : bf;
    const int n0  = blockIdx.y * 128;
    const int m0  = mblk * 128;
    const int tid = threadIdx.x;
    const int lane = tid & 31, wid = tid >> 5;
    const int warp_m = wid >> 2, warp_n = wid & 3;   // 2 x 4 warp grid

    __shared__ __align__(16) unsigned short Ah[128][24];
    __shared__ __align__(16) unsigned short Al[128][24];
    __shared__ __align__(16) unsigned short Bh[128][24];
    __shared__ __align__(16) unsigned short Bl[128][24];

    float cc[4][4][4];
    #pragma unroll
    for (int i = 0; i < 4; i++)
        #pragma unroll
        for (int j = 0; j < 4; j++)
            #pragma unroll
            for (int q = 0; q < 4; q++) cc[i][j][q] = 0.f;

    const int srow = tid >> 1;
    const int half = tid & 1;
    const int arow = sent[m0 + srow];
    const float* aptr = embed + (size_t)arow * DD + half * 8;
    const float* bptr = W + (size_t)(n0 + srow) * DD + half * 8;

    const unsigned ah_b = (unsigned)__cvta_generic_to_shared(&Ah[0][0]);
    const unsigned al_b = (unsigned)__cvta_generic_to_shared(&Al[0][0]);
    const unsigned bh_b = (unsigned)__cvta_generic_to_shared(&Bh[0][0]);
    const unsigned bl_b = (unsigned)__cvta_generic_to_shared(&Bl[0][0]);

    unsigned a_addr[4];
    #pragma unroll
    for (int mt = 0; mt < 4; mt++) {
        int row = warp_m * 64 + mt * 16 + (lane & 15);
        a_addr[mt] = row * 48 + ((lane >> 4) * 16);
    }
    unsigned b_addr[2];
    {
        int grp = lane >> 3, li = lane & 7;
        #pragma unroll
        for (int p = 0; p < 2; p++) {
            int row = warp_n * 32 + p * 16 + ((grp >> 1) * 8) + li;
            b_addr[p] = row * 48 + ((grp & 1) * 16);
        }
    }

    float4 pa0 = *(const float4*)(aptr);
    float4 pa1 = *(const float4*)(aptr + 4);
    float4 pb0 = *(const float4*)(bptr);
    float4 pb1 = *(const float4*)(bptr + 4);

    for (int k0 = 0; k0 < DD; k0 += 16) {
        unsigned auh[4], aul[4], buh[4], bul[4];
        cvt2(pa0.x, pa0.y, auh[0], aul[0]);
        cvt2(pa0.z, pa0.w, auh[1], aul[1]);
        cvt2(pa1.x, pa1.y, auh[2], aul[2]);
        cvt2(pa1.z, pa1.w, auh[3], aul[3]);
        cvt2(pb0.x, pb0.y, buh[0], bul[0]);
        cvt2(pb0.z, pb0.w, buh[1], bul[1]);
        cvt2(pb1.x, pb1.y, buh[2], bul[2]);
        cvt2(pb1.z, pb1.w, buh[3], bul[3]);

        __syncthreads();
        *(uint4*)&Ah[srow][half * 8] = make_uint4(auh[0], auh[1], auh[2], auh[3]);
        *(uint4*)&Al[srow][half * 8] = make_uint4(aul[0], aul[1], aul[2], aul[3]);
        *(uint4*)&Bh[srow][half * 8] = make_uint4(buh[0], buh[1], buh[2], buh[3]);
        *(uint4*)&Bl[srow][half * 8] = make_uint4(bul[0], bul[1], bul[2], bul[3]);
        __syncthreads();

        if (k0 + 16 < DD) {
            pa0 = *(const float4*)(aptr + k0 + 16);
            pa1 = *(const float4*)(aptr + k0 + 20);
            pb0 = *(const float4*)(bptr + k0 + 16);
            pb1 = *(const float4*)(bptr + k0 + 20);
        }

        unsigned fah[4][4], fal[4][4], fbh[2][4], fbl[2][4];
        #pragma unroll
        for (int mt = 0; mt < 4; mt++) {
            ldm_x4(fah[mt][0], fah[mt][1], fah[mt][2], fah[mt][3], ah_b + a_addr[mt]);
            ldm_x4(fal[mt][0], fal[mt][1], fal[mt][2], fal[mt][3], al_b + a_addr[mt]);
        }
        #pragma unroll
        for (int p = 0; p < 2; p++) {
            ldm_x4(fbh[p][0], fbh[p][1], fbh[p][2], fbh[p][3], bh_b + b_addr[p]);
            ldm_x4(fbl[p][0], fbl[p][1], fbl[p][2], fbl[p][3], bl_b + b_addr[p]);
        }

        #pragma unroll
        for (int mt = 0; mt < 4; mt++) {
            #pragma unroll
            for (int p = 0; p < 2; p++) {
                #pragma unroll
                for (int hh = 0; hh < 2; hh++) {
                    int nt = p * 2 + hh;
                    unsigned bh0 = fbh[p][hh * 2], bh1 = fbh[p][hh * 2 + 1];
                    unsigned bl0 = fbl[p][hh * 2], bl1 = fbl[p][hh * 2 + 1];
                    MMA16816(cc[mt][nt], fah[mt], bh0, bh1);
                    MMA16816(cc[mt][nt], fah[mt], bl0, bl1);
                    MMA16816(cc[mt][nt], fal[mt], bh0, bh1);
                }
            }
        }
    }

    #pragma unroll
    for (int mt = 0; mt < 4; mt++) {
        int row = m0 + warp_m * 64 + mt * 16 + (lane >> 2);
        #pragma unroll
        for (int nt = 0; nt < 4; nt++) {
            int col = n0 + warp_n * 32 + nt * 8 + (lane & 3) * 2;
            float b0v = bias[col], b1v = bias[col + 1];
            float2 v0 = {cc[mt][nt][0] + b0v, cc[mt][nt][1] + b1v};
            float2 v1 = {cc[mt][nt][2] + b0v, cc[mt][nt][3] + b1v};
            *(float2*)&g_pre[dir][row][col]     = v0;
            *(float2*)&g_pre[dir][row + 8][col] = v1;
        }
    }

    __threadfence();
    __syncthreads();
    if (tid == 0) atomicAdd(&g_pre_ready[dir][mblk], 1);
}

// ---------------- kernel 2: persistent bidirectional LSTM ----------------
// Staggered 2-deep poll: two loads kept ~RTT/2 apart in flight -> sampling
// period ~RTT/2 at the same poll traffic as before.
__global__ __launch_bounds__(256, 1) void lstm_kernel(
    const float* __restrict__ Whf, const float* __restrict__ Whb,
    const float* __restrict__ c0)
{
    const int bx  = blockIdx.x;
    const int dir = bx >> 6;
    const int g   = bx & 63;
    const int tid = threadIdx.x;
    const int w   = tid >> 5, l = tid & 31;
    const int j   = g * 8 + w;
    const int r   = l >> 3, s = l & 7;
    const float* __restrict__ Whh = dir ? Whb : Whf;

    float4 wv[16];
    {
        const float4* wrow = (const float4*)(Whh + (size_t)(r * HH + j) * HH + s * 64);
        #pragma unroll
        for (int q = 0; q < 16; q++) wv[q] = wrow[q];
    }

    float c = 0.f;
    if (l == 0) c = c0[dir * HH + j];

    __shared__ __align__(16) float hsm[2][8][68];   // parity x chunk x padded

    int last_mb = -1;

    for (int t = 0; t < SQ; ++t) {
        const int m = dir ? (SQ - 1 - t) : t;
        const int par = t & 1;

        const int mb = m >> 7;
        if (mb != last_mb) {
            const int* rc = &g_pre_ready[dir][mb];
            while (ld_acq(rc) < 16) { }
            last_mb = mb;
        }

        float pre = 0.f;
        if (s == 0) pre = g_pre[dir][m][r * HH + j];

        // staggered 2-deep poll: thread tid owns pairs (2*tid, 2*tid+1)
        {
            const uint4* pp = &g_hp[par][dir][tid];
            const unsigned tu = (unsigned)t;
            uint4 v = __ldcg(pp);
            if (v.y != tu || v.w != tu) {
                uint4 p1 = __ldcg(pp);       // slot 1 in flight
                __nanosleep(120);            // ~RTT/2 phase shift
                uint4 p0 = __ldcg(pp);       // slot 0 in flight, staggered
                for (;;) {
                    if (p1.y == tu && p1.w == tu) { v = p1; break; }
                    p1 = __ldcg(pp);
                    if (p0.y == tu && p0.w == tu) { v = p0; break; }
                    p0 = __ldcg(pp);
                }
            }
            const int e0 = 2 * tid;
            const int ch = e0 >> 6, off = e0 & 63;
            hsm[par][ch][off]     = __uint_as_float(v.x);
            hsm[par][ch][off + 1] = __uint_as_float(v.z);
        }
        __syncthreads();

        const float4* hp4 = (const float4*)&hsm[par][s][0];
        float a0 = pre, a1 = 0.f, a2 = 0.f, a3 = 0.f;
        #pragma unroll
        for (int q = 0; q < 4; q++) {
            float4 h0v = hp4[4*q+0], w0 = wv[4*q+0];
            float4 h1v = hp4[4*q+1], w1 = wv[4*q+1];
            float4 h2v = hp4[4*q+2], w2 = wv[4*q+2];
            float4 h3v = hp4[4*q+3], w3 = wv[4*q+3];
            a0 += w0.x*h0v.x + w0.y*h0v.y + w0.z*h0v.z + w0.w*h0v.w;
            a1 += w1.x*h1v.x + w1.y*h1v.y + w1.z*h1v.z + w1.w*h1v.w;
            a2 += w2.x*h2v.x + w2.y*h2v.y + w2.z*h2v.z + w2.w*h2v.w;
            a3 += w3.x*h3v.x + w3.y*h3v.y + w3.z*h3v.z + w3.w*h3v.w;
        }
        float acc = (a0 + a1) + (a2 + a3);

        acc += __shfl_xor_sync(0xffffffffu, acc, 1);
        acc += __shfl_xor_sync(0xffffffffu, acc, 2);
        acc += __shfl_xor_sync(0xffffffffu, acc, 4);

        float act = (r == 2) ? fast_tanh(acc) : fast_sig(acc);
        float p16 = __shfl_xor_sync(0xffffffffu, act, 16);
        float vv  = ((r & 1) == 0) ? act * p16 : act;
        float q8  = __shfl_xor_sync(0xffffffffu, vv, 8);
        float q8b = __shfl_xor_sync(0xffffffffu, p16, 8);

        if (l == 0) {
            c = q8 * c + vv;
            float h = q8b * fast_tanh(c);
            uint2* dst = (uint2*)&g_hp[(t + 1) & 1][dir][0];
            __stcg(&dst[j], make_uint2(__float_as_uint(h), (unsigned)(t + 1)));
            g_hout[dir][m][j] = h;
        }
    }
}

// ---------------- kernel 3: tag projection (8 positions per block) ----------------
__global__ void feats_kernel(const float* __restrict__ Wtag,
                             const float* __restrict__ btag)
{
    const int m0 = blockIdx.x * 8;
    const int tid = threadIdx.x;
    const int tag = tid >> 3, sub = tid & 7;
    const float* xbase = (sub < 4) ? &g_hout[0][0][0] : &g_hout[1][0][0];
    const int off = (sub & 3) * 128;
    const float* wp = Wtag + (size_t)tag * (2 * HH) + sub * 128;

    float s[8];
    #pragma unroll
    for (int mm = 0; mm < 8; mm++) s[mm] = 0.f;

    for (int i = 0; i < 32; i++) {
        float4 wv = *(const float4*)(wp + i * 4);
        #pragma unroll
        for (int mm = 0; mm < 8; mm++) {
            float4 xv = *(const float4*)(xbase + (size_t)(m0 + mm) * HH + off + i * 4);
            s[mm] += xv.x * wv.x + xv.y * wv.y + xv.z * wv.z + xv.w * wv.w;
        }
    }
    #pragma unroll
    for (int mm = 0; mm < 8; mm++) {
        s[mm] += __shfl_xor_sync(0xffffffffu, s[mm], 1);
        s[mm] += __shfl_xor_sync(0xffffffffu, s[mm], 2);
        s[mm] += __shfl_xor_sync(0xffffffffu, s[mm], 4);
    }
    if (sub == 0) {
        float b = btag[tag];
        #pragma unroll
        for (int mm = 0; mm < 8; mm++) g_feats[m0 + mm][tag] = s[mm] + b;
    }
}

// ---------------- kernel 4: Viterbi + backtrace (R7 version) ----------------
extern __shared__ char sm_raw[];

__global__ void viterbi_kernel(const float* __restrict__ trans,
                               const int* __restrict__ startp,
                               const int* __restrict__ stopp,
                               float* __restrict__ out)
{
    char*  bp   = sm_raw;
    float* fv   = (float*)(sm_raw + SQ * TT);
    float* term = fv + 32;
    const int n = threadIdx.x;
    const int start = *startp;
    const int stop  = *stopp;

    float trn[TT];
    if (n < TT) {
        #pragma unroll
        for (int p = 0; p < TT; p++) trn[p] = trans[n * TT + p];
        fv[n] = (n == start) ? 0.f : NEGV;
    }
    __syncwarp();

    float ft = (n < TT) ? g_feats[0][n] : 0.f;

    for (int t = 0; t < SQ; ++t) {
        float ftn = (n < TT && t + 1 < SQ) ? g_feats[t + 1][n] : 0.f;

        float fvn = 0.f;
        if (n < TT) {
            float s[TT];
            #pragma unroll
            for (int p = 0; p < TT; p++) s[p] = fv[p] + trn[p];
            float b0 = s[0];  int a0 = 0;
            #pragma unroll
            for (int p = 1; p < 5; p++)   if (s[p] > b0) { b0 = s[p]; a0 = p; }
            float b1 = s[5];  int a1 = 5;
            #pragma unroll
            for (int p = 6; p < 10; p++)  if (s[p] > b1) { b1 = s[p]; a1 = p; }
            float b2 = s[10]; int a2 = 10;
            #pragma unroll
            for (int p = 11; p < 15; p++) if (s[p] > b2) { b2 = s[p]; a2 = p; }
            float b3 = s[15]; int a3 = 15;
            #pragma unroll
            for (int p = 16; p < 20; p++) if (s[p] > b3) { b3 = s[p]; a3 = p; }
            if (b1 > b0) { b0 = b1; a0 = a1; }
            if (b3 > b2) { b2 = b3; a2 = a3; }
            if (b2 > b0) { b0 = b2; a0 = a2; }
            fvn = b0 + ft;
            bp[t * TT + n] = (char)a0;
        }
        __syncwarp();
        if (n < TT) fv[n] = fvn;
        __syncwarp();
        ft = ftn;
    }

    if (n < TT) term[n] = fv[n] + trans[stop * TT + n];
    __syncwarp();

    if (n == 0) {
        float best = term[0]; int bt = 0;
        #pragma unroll
        for (int p = 1; p < TT; p++) if (term[p] > best) { best = term[p]; bt = p; }
        out[0] = best;
        int tag = bt;
        out[SQ] = (float)bt;
        for (int t = SQ - 1; t >= 1; --t) {
            tag = bp[t * TT + tag];
            out[t] = (float)tag;
        }
    }
}

// ---------------- launcher: overlapped (R12 topology) ----------------
extern "C" void kernel_launch(void* const* d_in, const int* in_sizes, int n_in,
                              void* d_out, int out_size) {
    const int*   sent  = (const int*)  d_in[0];
    const float* embed = (const float*)d_in[1];
    const float* Wihf  = (const float*)d_in[2];
    const float* Whhf  = (const float*)d_in[3];
    const float* bf    = (const float*)d_in[4];
    const float* Wihb  = (const float*)d_in[5];
    const float* Whhb  = (const float*)d_in[6];
    const float* bb    = (const float*)d_in[7];
    const float* h0    = (const float*)d_in[8];
    const float* c0    = (const float*)d_in[9];
    const float* Wtag  = (const float*)d_in[10];
    const float* btag  = (const float*)d_in[11];
    const float* trans = (const float*)d_in[12];
    const int*   start = (const int*)  d_in[13];
    const int*   stop  = (const int*)  d_in[14];
    float* out = (float*)d_out;

    static cudaStream_t s_b = nullptr;
    static cudaEvent_t ev_fork = nullptr, ev_join = nullptr;
    if (s_b == nullptr) {
        int prio_lo = 0, prio_hi = 0;
        cudaDeviceGetStreamPriorityRange(&prio_lo, &prio_hi);
        cudaStreamCreateWithPriority(&s_b, cudaStreamNonBlocking, prio_lo);
        cudaEventCreateWithFlags(&ev_fork, cudaEventDisableTiming);
        cudaEventCreateWithFlags(&ev_join, cudaEventDisableTiming);
    }

    const int vit_smem = SQ * TT + 64 * 4 + 256;   // 82432 B
    cudaFuncSetAttribute(viterbi_kernel,
                         cudaFuncAttributeMaxDynamicSharedMemorySize, vit_smem);

    init_kernel<<<1, 1024>>>(h0);

    // fork: GEMM on low-priority side stream, LSTM on main stream
    cudaEventRecord(ev_fork, 0);
    cudaStreamWaitEvent(s_b, ev_fork, 0);
    gemm_pre_kernel<<<dim3(2, 16, 32), 256, 0, s_b>>>(sent, embed, Wihf, bf, Wihb, bb);
    lstm_kernel<<<128, 256>>>(Whhf, Whhb, c0);
    cudaEventRecord(ev_join, s_b);
    cudaStreamWaitEvent(0, ev_join, 0);

    dummy_kernel<<<1, 1>>>();
    feats_kernel<<<SQ / 8, 160>>>(Wtag, btag);
    viterbi_kernel<<<1, 32, vit_smem>>>(trans, start, stop, out);
}

// round 16
// speedup vs baseline: 1.9917x; 1.9917x over previous
#include <cuda_runtime.h>
#include <cuda_bf16.h>
#include <math.h>

#define SQ 4096
#define DD 1024
#define HH 512
#define TT 20
#define G4H 2048
#define NEGV -10000.0f

// ---------------- static scratch (allocation-free) ----------------
__device__ float g_pre[2][SQ][G4H];     // input projections + bias
__device__ float g_hout[2][SQ][HH];     // hidden states, natural position order
__device__ uint4 g_hp[2][2][HH / 2];    // [parity][dir][e]: {h(2e),tag, h(2e+1),tag}
__device__ int   g_pre_ready[2][32];    // per (dir, m-block) completed n-block count
__device__ float g_feats[SQ][TT];       // emission scores

__device__ __forceinline__ int ld_acq(const int* p) {
    int v; asm volatile("ld.acquire.gpu.global.b32 %0, [%1];" : "=r"(v) : "l"(p)); return v;
}

// fast activations: ex2.approx-based, ~1e-6 rel error, clamped (no inf/inf)
__device__ __forceinline__ float fast_sig(float x) {
    float e = __expf(-x);
    return __fdividef(1.f, 1.f + e);
}
__device__ __forceinline__ float fast_tanh(float x) {
    float xc = fminf(fmaxf(x, -15.f), 15.f);
    float e = __expf(2.f * xc);
    return __fdividef(e - 1.f, e + 1.f);
}

// bf16 split helpers: f = hi + lo with |dropped| ~ 2^-16 relative
__device__ __forceinline__ void cvt2(float f0, float f1, unsigned& uh, unsigned& ul) {
    __nv_bfloat16 h0 = __float2bfloat16(f0), h1 = __float2bfloat16(f1);
    float r0 = f0 - __bfloat162float(h0);
    float r1 = f1 - __bfloat162float(h1);
    __nv_bfloat16 l0 = __float2bfloat16(r0), l1 = __float2bfloat16(r1);
    uh = (unsigned)__bfloat16_as_ushort(h0) | ((unsigned)__bfloat16_as_ushort(h1) << 16);
    ul = (unsigned)__bfloat16_as_ushort(l0) | ((unsigned)__bfloat16_as_ushort(l1) << 16);
}

__device__ __forceinline__ void ldm_x4(unsigned& r0, unsigned& r1, unsigned& r2, unsigned& r3,
                                       unsigned addr) {
    asm volatile("ldmatrix.sync.aligned.m8n8.x4.shared.b16 {%0,%1,%2,%3}, [%4];"
                 : "=r"(r0), "=r"(r1), "=r"(r2), "=r"(r3) : "r"(addr));
}

#define MMA16816(c, a, b0, b1)                                              \
    asm volatile("mma.sync.aligned.m16n8k16.row.col.f32.bf16.bf16.f32 "     \
        "{%0,%1,%2,%3}, {%4,%5,%6,%7}, {%8,%9}, {%0,%1,%2,%3};"             \
        : "+f"((c)[0]), "+f"((c)[1]), "+f"((c)[2]), "+f"((c)[3])            \
        : "r"((a)[0]), "r"((a)[1]), "r"((a)[2]), "r"((a)[3]),               \
          "r"(b0), "r"(b1))

// ---------------- kernel 0: per-replay init ----------------
__global__ void init_kernel(const float* __restrict__ h0) {
    int t = threadIdx.x;                 // 1024 threads
    int dir = t >> 9, k = t & (HH - 1);
    uint2* even = (uint2*)&g_hp[0][dir][0];
    uint2* odd  = (uint2*)&g_hp[1][dir][0];
    even[k] = make_uint2(__float_as_uint(h0[dir * HH + k]), 0u);   // h_0, tag 0
    odd[k]  = make_uint2(0u, 0xFFFFFFFFu);                         // poison
    if (t < 64) ((int*)g_pre_ready)[t] = 0;
}

__global__ void dummy_kernel() {}

// ---------------- kernel 1: gather + input projection, tensor-core bf16-split ----------------
// D = Ah*Bh + Ah*Bl + Al*Bh (3-term double-bf16, fp32 accum), ~1e-5 relative error.
__global__ __launch_bounds__(256) void gemm_pre_kernel(
    const int* __restrict__ sent, const float* __restrict__ embed,
    const float* __restrict__ Wf, const float* __restrict__ bf,
    const float* __restrict__ Wb, const float* __restrict__ bb)
{
    const int dir   = blockIdx.x;
    const int mprio = blockIdx.z;
    const int mblk  = dir ? (31 - mprio) : mprio;
    const float* __restrict__ W    = dir ? Wb : Wf;
    const float* __restrict__ bias = dir ? bb : bf;
    const int n0  = blockIdx.y * 128;
    const int m0  = mblk * 128;
    const int tid = threadIdx.x;
    const int lane = tid & 31, wid = tid >> 5;
    const int warp_m = wid >> 2, warp_n = wid & 3;   // 2 x 4 warp grid

    __shared__ __align__(16) unsigned short Ah[128][24];
    __shared__ __align__(16) unsigned short Al[128][24];
    __shared__ __align__(16) unsigned short Bh[128][24];
    __shared__ __align__(16) unsigned short Bl[128][24];

    float cc[4][4][4];
    #pragma unroll
    for (int i = 0; i < 4; i++)
        #pragma unroll
        for (int j = 0; j < 4; j++)
            #pragma unroll
            for (int q = 0; q < 4; q++) cc[i][j][q] = 0.f;

    const int srow = tid >> 1;
    const int half = tid & 1;
    const int arow = sent[m0 + srow];
    const float* aptr = embed + (size_t)arow * DD + half * 8;
    const float* bptr = W + (size_t)(n0 + srow) * DD + half * 8;

    const unsigned ah_b = (unsigned)__cvta_generic_to_shared(&Ah[0][0]);
    const unsigned al_b = (unsigned)__cvta_generic_to_shared(&Al[0][0]);
    const unsigned bh_b = (unsigned)__cvta_generic_to_shared(&Bh[0][0]);
    const unsigned bl_b = (unsigned)__cvta_generic_to_shared(&Bl[0][0]);

    unsigned a_addr[4];
    #pragma unroll
    for (int mt = 0; mt < 4; mt++) {
        int row = warp_m * 64 + mt * 16 + (lane & 15);
        a_addr[mt] = row * 48 + ((lane >> 4) * 16);
    }
    unsigned b_addr[2];
    {
        int grp = lane >> 3, li = lane & 7;
        #pragma unroll
        for (int p = 0; p < 2; p++) {
            int row = warp_n * 32 + p * 16 + ((grp >> 1) * 8) + li;
            b_addr[p] = row * 48 + ((grp & 1) * 16);
        }
    }

    float4 pa0 = *(const float4*)(aptr);
    float4 pa1 = *(const float4*)(aptr + 4);
    float4 pb0 = *(const float4*)(bptr);
    float4 pb1 = *(const float4*)(bptr + 4);

    for (int k0 = 0; k0 < DD; k0 += 16) {
        unsigned auh[4], aul[4], buh[4], bul[4];
        cvt2(pa0.x, pa0.y, auh[0], aul[0]);
        cvt2(pa0.z, pa0.w, auh[1], aul[1]);
        cvt2(pa1.x, pa1.y, auh[2], aul[2]);
        cvt2(pa1.z, pa1.w, auh[3], aul[3]);
        cvt2(pb0.x, pb0.y, buh[0], bul[0]);
        cvt2(pb0.z, pb0.w, buh[1], bul[1]);
        cvt2(pb1.x, pb1.y, buh[2], bul[2]);
        cvt2(pb1.z, pb1.w, buh[3], bul[3]);

        __syncthreads();
        *(uint4*)&Ah[srow][half * 8] = make_uint4(auh[0], auh[1], auh[2], auh[3]);
        *(uint4*)&Al[srow][half * 8] = make_uint4(aul[0], aul[1], aul[2], aul[3]);
        *(uint4*)&Bh[srow][half * 8] = make_uint4(buh[0], buh[1], buh[2], buh[3]);
        *(uint4*)&Bl[srow][half * 8] = make_uint4(bul[0], bul[1], bul[2], bul[3]);
        __syncthreads();

        if (k0 + 16 < DD) {
            pa0 = *(const float4*)(aptr + k0 + 16);
            pa1 = *(const float4*)(aptr + k0 + 20);
            pb0 = *(const float4*)(bptr + k0 + 16);
            pb1 = *(const float4*)(bptr + k0 + 20);
        }

        unsigned fah[4][4], fal[4][4], fbh[2][4], fbl[2][4];
        #pragma unroll
        for (int mt = 0; mt < 4; mt++) {
            ldm_x4(fah[mt][0], fah[mt][1], fah[mt][2], fah[mt][3], ah_b + a_addr[mt]);
            ldm_x4(fal[mt][0], fal[mt][1], fal[mt][2], fal[mt][3], al_b + a_addr[mt]);
        }
        #pragma unroll
        for (int p = 0; p < 2; p++) {
            ldm_x4(fbh[p][0], fbh[p][1], fbh[p][2], fbh[p][3], bh_b + b_addr[p]);
            ldm_x4(fbl[p][0], fbl[p][1], fbl[p][2], fbl[p][3], bl_b + b_addr[p]);
        }

        #pragma unroll
        for (int mt = 0; mt < 4; mt++) {
            #pragma unroll
            for (int p = 0; p < 2; p++) {
                #pragma unroll
                for (int hh = 0; hh < 2; hh++) {
                    int nt = p * 2 + hh;
                    unsigned bh0 = fbh[p][hh * 2], bh1 = fbh[p][hh * 2 + 1];
                    unsigned bl0 = fbl[p][hh * 2], bl1 = fbl[p][hh * 2 + 1];
                    MMA16816(cc[mt][nt], fah[mt], bh0, bh1);
                    MMA16816(cc[mt][nt], fah[mt], bl0, bl1);
                    MMA16816(cc[mt][nt], fal[mt], bh0, bh1);
                }
            }
        }
    }

    #pragma unroll
    for (int mt = 0; mt < 4; mt++) {
        int row = m0 + warp_m * 64 + mt * 16 + (lane >> 2);
        #pragma unroll
        for (int nt = 0; nt < 4; nt++) {
            int col = n0 + warp_n * 32 + nt * 8 + (lane & 3) * 2;
            float b0v = bias[col], b1v = bias[col + 1];
            float2 v0 = {cc[mt][nt][0] + b0v, cc[mt][nt][1] + b1v};
            float2 v1 = {cc[mt][nt][2] + b0v, cc[mt][nt][3] + b1v};
            *(float2*)&g_pre[dir][row][col]     = v0;
            *(float2*)&g_pre[dir][row + 8][col] = v1;
        }
    }

    __threadfence();
    __syncthreads();
    if (tid == 0) atomicAdd(&g_pre_ready[dir][mblk], 1);
}

// ---------------- kernel 2: persistent bidirectional LSTM (R12 version, DO NOT TOUCH) ----------------
__global__ __launch_bounds__(256, 1) void lstm_kernel(
    const float* __restrict__ Whf, const float* __restrict__ Whb,
    const float* __restrict__ c0)
{
    const int bx  = blockIdx.x;
    const int dir = bx >> 6;
    const int g   = bx & 63;
    const int tid = threadIdx.x;
    const int w   = tid >> 5, l = tid & 31;
    const int j   = g * 8 + w;
    const int r   = l >> 3, s = l & 7;
    const float* __restrict__ Whh = dir ? Whb : Whf;

    float4 wv[16];
    {
        const float4* wrow = (const float4*)(Whh + (size_t)(r * HH + j) * HH + s * 64);
        #pragma unroll
        for (int q = 0; q < 16; q++) wv[q] = wrow[q];
    }

    float c = 0.f;
    if (l == 0) c = c0[dir * HH + j];

    __shared__ __align__(16) float hsm[2][8][68];   // parity x chunk x padded

    int last_mb = -1;

    for (int t = 0; t < SQ; ++t) {
        const int m = dir ? (SQ - 1 - t) : t;
        const int par = t & 1;

        const int mb = m >> 7;
        if (mb != last_mb) {
            const int* rc = &g_pre_ready[dir][mb];
            while (ld_acq(rc) < 16) { }
            last_mb = mb;
        }

        float pre = 0.f;
        if (s == 0) pre = g_pre[dir][m][r * HH + j];

        {
            const uint4* pp = &g_hp[par][dir][tid];
            uint4 v = __ldcg(pp);
            if (v.y != (unsigned)t || v.w != (unsigned)t) {
                for (;;) {
                    uint4 a = __ldcg(pp);
                    uint4 b = __ldcg(pp);
                    if (a.y == (unsigned)t && a.w == (unsigned)t) { v = a; break; }
                    if (b.y == (unsigned)t && b.w == (unsigned)t) { v = b; break; }
                }
            }
            const int e0 = 2 * tid;
            const int ch = e0 >> 6, off = e0 & 63;
            hsm[par][ch][off]     = __uint_as_float(v.x);
            hsm[par][ch][off + 1] = __uint_as_float(v.z);
        }
        __syncthreads();

        const float4* hp4 = (const float4*)&hsm[par][s][0];
        float a0 = pre, a1 = 0.f, a2 = 0.f, a3 = 0.f;
        #pragma unroll
        for (int q = 0; q < 4; q++) {
            float4 h0v = hp4[4*q+0], w0 = wv[4*q+0];
            float4 h1v = hp4[4*q+1], w1 = wv[4*q+1];
            float4 h2v = hp4[4*q+2], w2 = wv[4*q+2];
            float4 h3v = hp4[4*q+3], w3 = wv[4*q+3];
            a0 += w0.x*h0v.x + w0.y*h0v.y + w0.z*h0v.z + w0.w*h0v.w;
            a1 += w1.x*h1v.x + w1.y*h1v.y + w1.z*h1v.z + w1.w*h1v.w;
            a2 += w2.x*h2v.x + w2.y*h2v.y + w2.z*h2v.z + w2.w*h2v.w;
            a3 += w3.x*h3v.x + w3.y*h3v.y + w3.z*h3v.z + w3.w*h3v.w;
        }
        float acc = (a0 + a1) + (a2 + a3);

        acc += __shfl_xor_sync(0xffffffffu, acc, 1);
        acc += __shfl_xor_sync(0xffffffffu, acc, 2);
        acc += __shfl_xor_sync(0xffffffffu, acc, 4);

        float act = (r == 2) ? fast_tanh(acc) : fast_sig(acc);
        float p16 = __shfl_xor_sync(0xffffffffu, act, 16);
        float vv  = ((r & 1) == 0) ? act * p16 : act;
        float q8  = __shfl_xor_sync(0xffffffffu, vv, 8);
        float q8b = __shfl_xor_sync(0xffffffffu, p16, 8);

        if (l == 0) {
            c = q8 * c + vv;
            float h = q8b * fast_tanh(c);
            uint2* dst = (uint2*)&g_hp[(t + 1) & 1][dir][0];
            __stcg(&dst[j], make_uint2(__float_as_uint(h), (unsigned)(t + 1)));
            g_hout[dir][m][j] = h;
        }
    }
}

// ---------------- kernel 3: tag projection (8 positions per block) ----------------
__global__ void feats_kernel(const float* __restrict__ Wtag,
                             const float* __restrict__ btag)
{
    const int m0 = blockIdx.x * 8;
    const int tid = threadIdx.x;
    const int tag = tid >> 3, sub = tid & 7;
    const float* xbase = (sub < 4) ? &g_hout[0][0][0] : &g_hout[1][0][0];
    const int off = (sub & 3) * 128;
    const float* wp = Wtag + (size_t)tag * (2 * HH) + sub * 128;

    float s[8];
    #pragma unroll
    for (int mm = 0; mm < 8; mm++) s[mm] = 0.f;

    for (int i = 0; i < 32; i++) {
        float4 wv = *(const float4*)(wp + i * 4);
        #pragma unroll
        for (int mm = 0; mm < 8; mm++) {
            float4 xv = *(const float4*)(xbase + (size_t)(m0 + mm) * HH + off + i * 4);
            s[mm] += xv.x * wv.x + xv.y * wv.y + xv.z * wv.z + xv.w * wv.w;
        }
    }
    #pragma unroll
    for (int mm = 0; mm < 8; mm++) {
        s[mm] += __shfl_xor_sync(0xffffffffu, s[mm], 1);
        s[mm] += __shfl_xor_sync(0xffffffffu, s[mm], 2);
        s[mm] += __shfl_xor_sync(0xffffffffu, s[mm], 4);
    }
    if (sub == 0) {
        float b = btag[tag];
        #pragma unroll
        for (int mm = 0; mm < 8; mm++) g_feats[m0 + mm][tag] = s[mm] + b;
    }
}

// ---------------- kernel 4: Viterbi + backtrace (smem fv + max-tree/ffs argmax) ----------------
extern __shared__ char sm_raw[];

__global__ void viterbi_kernel(const float* __restrict__ trans,
                               const int* __restrict__ startp,
                               const int* __restrict__ stopp,
                               float* __restrict__ out)
{
    char*  bp   = sm_raw;                         // [SQ][TT] backpointers
    float* fv   = (float*)(sm_raw + SQ * TT);     // [32]
    float* term = fv + 32;                        // [32]
    const int n = threadIdx.x;                    // lane = next-tag
    const int start = *startp;
    const int stop  = *stopp;

    float trn[TT];
    if (n < TT) {
        #pragma unroll
        for (int p = 0; p < TT; p++) trn[p] = trans[n * TT + p];
        fv[n] = (n == start) ? 0.f : NEGV;
    }
    __syncwarp();

    float ft = (n < TT) ? g_feats[0][n] : 0.f;

    for (int t = 0; t < SQ; ++t) {
        float ftn = (n < TT && t + 1 < SQ) ? g_feats[t + 1][n] : 0.f;

        float fvn = 0.f;
        if (n < TT) {
            float s[TT];
            #pragma unroll
            for (int p = 0; p < TT; p++) s[p] = fv[p] + trn[p];

            // max tree: exact same max value as the sequential scan (max is exact)
            float m01 = fmaxf(s[0],  s[1]),  m23 = fmaxf(s[2],  s[3]);
            float m45 = fmaxf(s[4],  s[5]),  m67 = fmaxf(s[6],  s[7]);
            float m89 = fmaxf(s[8],  s[9]),  mab = fmaxf(s[10], s[11]);
            float mcd = fmaxf(s[12], s[13]), mef = fmaxf(s[14], s[15]);
            float mgh = fmaxf(s[16], s[17]), mij = fmaxf(s[18], s[19]);
            float q0 = fmaxf(m01, m23), q1 = fmaxf(m45, m67);
            float q2 = fmaxf(m89, mab), q3 = fmaxf(mcd, mef);
            float q4 = fmaxf(mgh, mij);
            float best = fmaxf(fmaxf(fmaxf(q0, q1), fmaxf(q2, q3)), q4);

            // first index attaining the max == jnp.argmax first-max semantics
            unsigned msk = 0u;
            #pragma unroll
            for (int p = 0; p < TT; p++)
                msk |= (s[p] == best) ? (1u << p) : 0u;
            int arg = __ffs(msk) - 1;

            fvn = best + ft;
            bp[t * TT + n] = (char)arg;
        }
        __syncwarp();
        if (n < TT) fv[n] = fvn;
        __syncwarp();
        ft = ftn;
    }

    if (n < TT) term[n] = fv[n] + trans[stop * TT + n];
    __syncwarp();

    if (n == 0) {
        float best = term[0]; int bt = 0;
        #pragma unroll
        for (int p = 1; p < TT; p++) if (term[p] > best) { best = term[p]; bt = p; }
        out[0] = best;
        int tag = bt;
        out[SQ] = (float)bt;
        for (int t = SQ - 1; t >= 1; --t) {
            tag = bp[t * TT + tag];
            out[t] = (float)tag;
        }
    }
}

// ---------------- launcher: overlapped (R12 topology) ----------------
extern "C" void kernel_launch(void* const* d_in, const int* in_sizes, int n_in,
                              void* d_out, int out_size) {
    const int*   sent  = (const int*)  d_in[0];
    const float* embed = (const float*)d_in[1];
    const float* Wihf  = (const float*)d_in[2];
    const float* Whhf  = (const float*)d_in[3];
    const float* bf    = (const float*)d_in[4];
    const float* Wihb  = (const float*)d_in[5];
    const float* Whhb  = (const float*)d_in[6];
    const float* bb    = (const float*)d_in[7];
    const float* h0    = (const float*)d_in[8];
    const float* c0    = (const float*)d_in[9];
    const float* Wtag  = (const float*)d_in[10];
    const float* btag  = (const float*)d_in[11];
    const float* trans = (const float*)d_in[12];
    const int*   start = (const int*)  d_in[13];
    const int*   stop  = (const int*)  d_in[14];
    float* out = (float*)d_out;

    static cudaStream_t s_b = nullptr;
    static cudaEvent_t ev_fork = nullptr, ev_join = nullptr;
    if (s_b == nullptr) {
        int prio_lo = 0, prio_hi = 0;
        cudaDeviceGetStreamPriorityRange(&prio_lo, &prio_hi);
        cudaStreamCreateWithPriority(&s_b, cudaStreamNonBlocking, prio_lo);
        cudaEventCreateWithFlags(&ev_fork, cudaEventDisableTiming);
        cudaEventCreateWithFlags(&ev_join, cudaEventDisableTiming);
    }

    const int vit_smem = SQ * TT + 64 * 4 + 256;   // 82432 B
    cudaFuncSetAttribute(viterbi_kernel,
                         cudaFuncAttributeMaxDynamicSharedMemorySize, vit_smem);

    init_kernel<<<1, 1024>>>(h0);

    // fork: GEMM on low-priority side stream, LSTM on main stream
    cudaEventRecord(ev_fork, 0);
    cudaStreamWaitEvent(s_b, ev_fork, 0);
    gemm_pre_kernel<<<dim3(2, 16, 32), 256, 0, s_b>>>(sent, embed, Wihf, bf, Wihb, bb);
    lstm_kernel<<<128, 256>>>(Whhf, Whhb, c0);
    cudaEventRecord(ev_join, s_b);
    cudaStreamWaitEvent(0, ev_join, 0);

    dummy_kernel<<<1, 1>>>();
    feats_kernel<<<SQ / 8, 160>>>(Wtag, btag);
    viterbi_kernel<<<1, 32, vit_smem>>>(trans, start, stop, out);
}

// round 17
// speedup vs baseline: 2.3097x; 1.1596x over previous
#include <cuda_runtime.h>
#include <cuda_bf16.h>
#include <math.h>

#define SQ 4096
#define DD 1024
#define HH 512
#define TT 20
#define G4H 2048
#define NEGV -10000.0f
#define NB 128
#define BSV 32

// ---------------- static scratch (allocation-free) ----------------
__device__ float g_pre[2][SQ][G4H];     // input projections + bias
__device__ float g_hout[2][SQ][HH];     // hidden states, natural position order
__device__ uint4 g_hp[2][2][HH / 2];    // [parity][dir][e]: {h(2e),tag, h(2e+1),tag}
__device__ int   g_pre_ready[2][32];    // per (dir, m-block) completed n-block count
__device__ float g_feats[SQ][TT];       // emission scores
// viterbi scan scratch
__device__ float g_blockC[NB][TT][TT];          // composed block matrices
__device__ float g_fvs[NB + 1][TT];             // fv at each block boundary
__device__ unsigned char g_pathtab[NB][TT][BSV];// per end-tag in-block paths
__device__ unsigned char g_entrytab[NB][TT];    // per end-tag entry tag

__device__ __forceinline__ int ld_acq(const int* p) {
    int v; asm volatile("ld.acquire.gpu.global.b32 %0, [%1];" : "=r"(v) : "l"(p)); return v;
}

// fast activations: ex2.approx-based, ~1e-6 rel error, clamped (no inf/inf)
__device__ __forceinline__ float fast_sig(float x) {
    float e = __expf(-x);
    return __fdividef(1.f, 1.f + e);
}
__device__ __forceinline__ float fast_tanh(float x) {
    float xc = fminf(fmaxf(x, -15.f), 15.f);
    float e = __expf(2.f * xc);
    return __fdividef(e - 1.f, e + 1.f);
}

// bf16 split helpers: f = hi + lo with |dropped| ~ 2^-16 relative
__device__ __forceinline__ void cvt2(float f0, float f1, unsigned& uh, unsigned& ul) {
    __nv_bfloat16 h0 = __float2bfloat16(f0), h1 = __float2bfloat16(f1);
    float r0 = f0 - __bfloat162float(h0);
    float r1 = f1 - __bfloat162float(h1);
    __nv_bfloat16 l0 = __float2bfloat16(r0), l1 = __float2bfloat16(r1);
    uh = (unsigned)__bfloat16_as_ushort(h0) | ((unsigned)__bfloat16_as_ushort(h1) << 16);
    ul = (unsigned)__bfloat16_as_ushort(l0) | ((unsigned)__bfloat16_as_ushort(l1) << 16);
}

__device__ __forceinline__ void ldm_x4(unsigned& r0, unsigned& r1, unsigned& r2, unsigned& r3,
                                       unsigned addr) {
    asm volatile("ldmatrix.sync.aligned.m8n8.x4.shared.b16 {%0,%1,%2,%3}, [%4];"
                 : "=r"(r0), "=r"(r1), "=r"(r2), "=r"(r3) : "r"(addr));
}

#define MMA16816(c, a, b0, b1)                                              \
    asm volatile("mma.sync.aligned.m16n8k16.row.col.f32.bf16.bf16.f32 "     \
        "{%0,%1,%2,%3}, {%4,%5,%6,%7}, {%8,%9}, {%0,%1,%2,%3};"             \
        : "+f"((c)[0]), "+f"((c)[1]), "+f"((c)[2]), "+f"((c)[3])            \
        : "r"((a)[0]), "r"((a)[1]), "r"((a)[2]), "r"((a)[3]),               \
          "r"(b0), "r"(b1))

// ---------------- kernel 0: per-replay init ----------------
__global__ void init_kernel(const float* __restrict__ h0) {
    int t = threadIdx.x;                 // 1024 threads
    int dir = t >> 9, k = t & (HH - 1);
    uint2* even = (uint2*)&g_hp[0][dir][0];
    uint2* odd  = (uint2*)&g_hp[1][dir][0];
    even[k] = make_uint2(__float_as_uint(h0[dir * HH + k]), 0u);   // h_0, tag 0
    odd[k]  = make_uint2(0u, 0xFFFFFFFFu);                         // poison
    if (t < 64) ((int*)g_pre_ready)[t] = 0;
}

__global__ void dummy_kernel() {}

// ---------------- kernel 1: gather + input projection, tensor-core bf16-split ----------------
// D = Ah*Bh + Ah*Bl + Al*Bh (3-term double-bf16, fp32 accum), ~1e-5 relative error.
__global__ __launch_bounds__(256) void gemm_pre_kernel(
    const int* __restrict__ sent, const float* __restrict__ embed,
    const float* __restrict__ Wf, const float* __restrict__ bf,
    const float* __restrict__ Wb, const float* __restrict__ bb)
{
    const int dir   = blockIdx.x;
    const int mprio = blockIdx.z;
    const int mblk  = dir ? (31 - mprio) : mprio;
    const float* __restrict__ W    = dir ? Wb : Wf;
    const float* __restrict__ bias = dir ? bb : bf;
    const int n0  = blockIdx.y * 128;
    const int m0  = mblk * 128;
    const int tid = threadIdx.x;
    const int lane = tid & 31, wid = tid >> 5;
    const int warp_m = wid >> 2, warp_n = wid & 3;   // 2 x 4 warp grid

    __shared__ __align__(16) unsigned short Ah[128][24];
    __shared__ __align__(16) unsigned short Al[128][24];
    __shared__ __align__(16) unsigned short Bh[128][24];
    __shared__ __align__(16) unsigned short Bl[128][24];

    float cc[4][4][4];
    #pragma unroll
    for (int i = 0; i < 4; i++)
        #pragma unroll
        for (int j = 0; j < 4; j++)
            #pragma unroll
            for (int q = 0; q < 4; q++) cc[i][j][q] = 0.f;

    const int srow = tid >> 1;
    const int half = tid & 1;
    const int arow = sent[m0 + srow];
    const float* aptr = embed + (size_t)arow * DD + half * 8;
    const float* bptr = W + (size_t)(n0 + srow) * DD + half * 8;

    const unsigned ah_b = (unsigned)__cvta_generic_to_shared(&Ah[0][0]);
    const unsigned al_b = (unsigned)__cvta_generic_to_shared(&Al[0][0]);
    const unsigned bh_b = (unsigned)__cvta_generic_to_shared(&Bh[0][0]);
    const unsigned bl_b = (unsigned)__cvta_generic_to_shared(&Bl[0][0]);

    unsigned a_addr[4];
    #pragma unroll
    for (int mt = 0; mt < 4; mt++) {
        int row = warp_m * 64 + mt * 16 + (lane & 15);
        a_addr[mt] = row * 48 + ((lane >> 4) * 16);
    }
    unsigned b_addr[2];
    {
        int grp = lane >> 3, li = lane & 7;
        #pragma unroll
        for (int p = 0; p < 2; p++) {
            int row = warp_n * 32 + p * 16 + ((grp >> 1) * 8) + li;
            b_addr[p] = row * 48 + ((grp & 1) * 16);
        }
    }

    float4 pa0 = *(const float4*)(aptr);
    float4 pa1 = *(const float4*)(aptr + 4);
    float4 pb0 = *(const float4*)(bptr);
    float4 pb1 = *(const float4*)(bptr + 4);

    for (int k0 = 0; k0 < DD; k0 += 16) {
        unsigned auh[4], aul[4], buh[4], bul[4];
        cvt2(pa0.x, pa0.y, auh[0], aul[0]);
        cvt2(pa0.z, pa0.w, auh[1], aul[1]);
        cvt2(pa1.x, pa1.y, auh[2], aul[2]);
        cvt2(pa1.z, pa1.w, auh[3], aul[3]);
        cvt2(pb0.x, pb0.y, buh[0], bul[0]);
        cvt2(pb0.z, pb0.w, buh[1], bul[1]);
        cvt2(pb1.x, pb1.y, buh[2], bul[2]);
        cvt2(pb1.z, pb1.w, buh[3], bul[3]);

        __syncthreads();
        *(uint4*)&Ah[srow][half * 8] = make_uint4(auh[0], auh[1], auh[2], auh[3]);
        *(uint4*)&Al[srow][half * 8] = make_uint4(aul[0], aul[1], aul[2], aul[3]);
        *(uint4*)&Bh[srow][half * 8] = make_uint4(buh[0], buh[1], buh[2], buh[3]);
        *(uint4*)&Bl[srow][half * 8] = make_uint4(bul[0], bul[1], bul[2], bul[3]);
        __syncthreads();

        if (k0 + 16 < DD) {
            pa0 = *(const float4*)(aptr + k0 + 16);
            pa1 = *(const float4*)(aptr + k0 + 20);
            pb0 = *(const float4*)(bptr + k0 + 16);
            pb1 = *(const float4*)(bptr + k0 + 20);
        }

        unsigned fah[4][4], fal[4][4], fbh[2][4], fbl[2][4];
        #pragma unroll
        for (int mt = 0; mt < 4; mt++) {
            ldm_x4(fah[mt][0], fah[mt][1], fah[mt][2], fah[mt][3], ah_b + a_addr[mt]);
            ldm_x4(fal[mt][0], fal[mt][1], fal[mt][2], fal[mt][3], al_b + a_addr[mt]);
        }
        #pragma unroll
        for (int p = 0; p < 2; p++) {
            ldm_x4(fbh[p][0], fbh[p][1], fbh[p][2], fbh[p][3], bh_b + b_addr[p]);
            ldm_x4(fbl[p][0], fbl[p][1], fbl[p][2], fbl[p][3], bl_b + b_addr[p]);
        }

        #pragma unroll
        for (int mt = 0; mt < 4; mt++) {
            #pragma unroll
            for (int p = 0; p < 2; p++) {
                #pragma unroll
                for (int hh = 0; hh < 2; hh++) {
                    int nt = p * 2 + hh;
                    unsigned bh0 = fbh[p][hh * 2], bh1 = fbh[p][hh * 2 + 1];
                    unsigned bl0 = fbl[p][hh * 2], bl1 = fbl[p][hh * 2 + 1];
                    MMA16816(cc[mt][nt], fah[mt], bh0, bh1);
                    MMA16816(cc[mt][nt], fah[mt], bl0, bl1);
                    MMA16816(cc[mt][nt], fal[mt], bh0, bh1);
                }
            }
        }
    }

    #pragma unroll
    for (int mt = 0; mt < 4; mt++) {
        int row = m0 + warp_m * 64 + mt * 16 + (lane >> 2);
        #pragma unroll
        for (int nt = 0; nt < 4; nt++) {
            int col = n0 + warp_n * 32 + nt * 8 + (lane & 3) * 2;
            float b0v = bias[col], b1v = bias[col + 1];
            float2 v0 = {cc[mt][nt][0] + b0v, cc[mt][nt][1] + b1v};
            float2 v1 = {cc[mt][nt][2] + b0v, cc[mt][nt][3] + b1v};
            *(float2*)&g_pre[dir][row][col]     = v0;
            *(float2*)&g_pre[dir][row + 8][col] = v1;
        }
    }

    __threadfence();
    __syncthreads();
    if (tid == 0) atomicAdd(&g_pre_ready[dir][mblk], 1);
}

// ---------------- kernel 2: persistent bidirectional LSTM (R12 version, DO NOT TOUCH) ----------------
__global__ __launch_bounds__(256, 1) void lstm_kernel(
    const float* __restrict__ Whf, const float* __restrict__ Whb,
    const float* __restrict__ c0)
{
    const int bx  = blockIdx.x;
    const int dir = bx >> 6;
    const int g   = bx & 63;
    const int tid = threadIdx.x;
    const int w   = tid >> 5, l = tid & 31;
    const int j   = g * 8 + w;
    const int r   = l >> 3, s = l & 7;
    const float* __restrict__ Whh = dir ? Whb : Whf;

    float4 wv[16];
    {
        const float4* wrow = (const float4*)(Whh + (size_t)(r * HH + j) * HH + s * 64);
        #pragma unroll
        for (int q = 0; q < 16; q++) wv[q] = wrow[q];
    }

    float c = 0.f;
    if (l == 0) c = c0[dir * HH + j];

    __shared__ __align__(16) float hsm[2][8][68];   // parity x chunk x padded

    int last_mb = -1;

    for (int t = 0; t < SQ; ++t) {
        const int m = dir ? (SQ - 1 - t) : t;
        const int par = t & 1;

        const int mb = m >> 7;
        if (mb != last_mb) {
            const int* rc = &g_pre_ready[dir][mb];
            while (ld_acq(rc) < 16) { }
            last_mb = mb;
        }

        float pre = 0.f;
        if (s == 0) pre = g_pre[dir][m][r * HH + j];

        {
            const uint4* pp = &g_hp[par][dir][tid];
            uint4 v = __ldcg(pp);
            if (v.y != (unsigned)t || v.w != (unsigned)t) {
                for (;;) {
                    uint4 a = __ldcg(pp);
                    uint4 b = __ldcg(pp);
                    if (a.y == (unsigned)t && a.w == (unsigned)t) { v = a; break; }
                    if (b.y == (unsigned)t && b.w == (unsigned)t) { v = b; break; }
                }
            }
            const int e0 = 2 * tid;
            const int ch = e0 >> 6, off = e0 & 63;
            hsm[par][ch][off]     = __uint_as_float(v.x);
            hsm[par][ch][off + 1] = __uint_as_float(v.z);
        }
        __syncthreads();

        const float4* hp4 = (const float4*)&hsm[par][s][0];
        float a0 = pre, a1 = 0.f, a2 = 0.f, a3 = 0.f;
        #pragma unroll
        for (int q = 0; q < 4; q++) {
            float4 h0v = hp4[4*q+0], w0 = wv[4*q+0];
            float4 h1v = hp4[4*q+1], w1 = wv[4*q+1];
            float4 h2v = hp4[4*q+2], w2 = wv[4*q+2];
            float4 h3v = hp4[4*q+3], w3 = wv[4*q+3];
            a0 += w0.x*h0v.x + w0.y*h0v.y + w0.z*h0v.z + w0.w*h0v.w;
            a1 += w1.x*h1v.x + w1.y*h1v.y + w1.z*h1v.z + w1.w*h1v.w;
            a2 += w2.x*h2v.x + w2.y*h2v.y + w2.z*h2v.z + w2.w*h2v.w;
            a3 += w3.x*h3v.x + w3.y*h3v.y + w3.z*h3v.z + w3.w*h3v.w;
        }
        float acc = (a0 + a1) + (a2 + a3);

        acc += __shfl_xor_sync(0xffffffffu, acc, 1);
        acc += __shfl_xor_sync(0xffffffffu, acc, 2);
        acc += __shfl_xor_sync(0xffffffffu, acc, 4);

        float act = (r == 2) ? fast_tanh(acc) : fast_sig(acc);
        float p16 = __shfl_xor_sync(0xffffffffu, act, 16);
        float vv  = ((r & 1) == 0) ? act * p16 : act;
        float q8  = __shfl_xor_sync(0xffffffffu, vv, 8);
        float q8b = __shfl_xor_sync(0xffffffffu, p16, 8);

        if (l == 0) {
            c = q8 * c + vv;
            float h = q8b * fast_tanh(c);
            uint2* dst = (uint2*)&g_hp[(t + 1) & 1][dir][0];
            __stcg(&dst[j], make_uint2(__float_as_uint(h), (unsigned)(t + 1)));
            g_hout[dir][m][j] = h;
        }
    }
}

// ---------------- kernel 3: tag projection (8 positions per block) ----------------
__global__ void feats_kernel(const float* __restrict__ Wtag,
                             const float* __restrict__ btag)
{
    const int m0 = blockIdx.x * 8;
    const int tid = threadIdx.x;
    const int tag = tid >> 3, sub = tid & 7;
    const float* xbase = (sub < 4) ? &g_hout[0][0][0] : &g_hout[1][0][0];
    const int off = (sub & 3) * 128;
    const float* wp = Wtag + (size_t)tag * (2 * HH) + sub * 128;

    float s[8];
    #pragma unroll
    for (int mm = 0; mm < 8; mm++) s[mm] = 0.f;

    for (int i = 0; i < 32; i++) {
        float4 wv = *(const float4*)(wp + i * 4);
        #pragma unroll
        for (int mm = 0; mm < 8; mm++) {
            float4 xv = *(const float4*)(xbase + (size_t)(m0 + mm) * HH + off + i * 4);
            s[mm] += xv.x * wv.x + xv.y * wv.y + xv.z * wv.z + xv.w * wv.w;
        }
    }
    #pragma unroll
    for (int mm = 0; mm < 8; mm++) {
        s[mm] += __shfl_xor_sync(0xffffffffu, s[mm], 1);
        s[mm] += __shfl_xor_sync(0xffffffffu, s[mm], 2);
        s[mm] += __shfl_xor_sync(0xffffffffu, s[mm], 4);
    }
    if (sub == 0) {
        float b = btag[tag];
        #pragma unroll
        for (int mm = 0; mm < 8; mm++) g_feats[m0 + mm][tag] = s[mm] + b;
    }
}

// ---------------- kernel 4a: compose 32-step max-plus block matrices ----------------
// C_block = M_0 ∘ M_1 ∘ ... (left-assoc), M_s[i][j] = trans[i][j] + feat[s][i].
__global__ __launch_bounds__(400) void vit_compose_kernel(const float* __restrict__ trans)
{
    __shared__ float tr[TT * TT];
    __shared__ float fb[BSV][TT];
    __shared__ float Ca[TT * TT], Cb[TT * TT];
    const int b = blockIdx.x;
    const int tid = threadIdx.x;          // 400 threads
    if (tid < TT * TT) tr[tid] = trans[tid];
    for (int x = tid; x < BSV * TT; x += 400)
        fb[x / TT][x % TT] = g_feats[b * BSV + x / TT][x % TT];
    __syncthreads();

    const int i = tid / TT, j = tid % TT;
    float* cur = Ca; float* nxt = Cb;
    cur[i * TT + j] = tr[i * TT + j] + fb[0][i];
    __syncthreads();
    for (int s = 1; s < BSV; s++) {
        float best = cur[0 * TT + j] + tr[i * TT + 0];
        #pragma unroll
        for (int k = 1; k < TT; k++)
            best = fmaxf(best, cur[k * TT + j] + tr[i * TT + k]);
        nxt[i * TT + j] = best + fb[s][i];
        __syncthreads();
        float* tmp = cur; cur = nxt; nxt = tmp;
    }
    g_blockC[b][i][j] = cur[i * TT + j];
}

// ---------------- kernel 4b: scan fv through the 128 block matrices ----------------
__global__ __launch_bounds__(400) void vit_scan_kernel(const int* __restrict__ startp)
{
    __shared__ float fv[TT], fvn[TT];
    __shared__ float C[TT * TT];
    const int tid = threadIdx.x;          // 400 threads
    const int start = *startp;
    if (tid < TT) {
        fv[tid] = (tid == start) ? 0.f : NEGV;
        g_fvs[0][tid] = fv[tid];
    }
    __syncthreads();
    for (int b = 0; b < NB; b++) {
        C[tid] = g_blockC[b][tid / TT][tid % TT];
        __syncthreads();
        if (tid < TT) {
            float best = fv[0] + C[tid * TT + 0];
            #pragma unroll
            for (int k = 1; k < TT; k++)
                best = fmaxf(best, fv[k] + C[tid * TT + k]);
            fvn[tid] = best;
        }
        __syncthreads();
        if (tid < TT) {
            fv[tid] = fvn[tid];
            g_fvs[b + 1][tid] = fvn[tid];
        }
        __syncthreads();
    }
}

// ---------------- kernel 4c: in-block sequential Viterbi + per-end-tag backwalk ----------------
__global__ __launch_bounds__(32) void vit_block_kernel(const float* __restrict__ trans)
{
    __shared__ unsigned char bp[BSV][TT];
    __shared__ float fv[32];
    const int b = blockIdx.x;
    const int n = threadIdx.x;            // 32 threads, lane = next-tag

    float trn[TT];
    #pragma unroll
    for (int p = 0; p < TT; p++) trn[p] = (n < TT) ? trans[n * TT + p] : NEGV;
    if (n < TT) fv[n] = g_fvs[b][n];
    __syncwarp();

    for (int s = 0; s < BSV; s++) {
        float ft = (n < TT) ? g_feats[b * BSV + s][n] : 0.f;
        float fvn = 0.f;
        if (n < TT) {
            float sv[TT];
            #pragma unroll
            for (int p = 0; p < TT; p++) sv[p] = fv[p] + trn[p];
            float b0 = sv[0];  int a0 = 0;
            #pragma unroll
            for (int p = 1; p < 5; p++)   if (sv[p] > b0) { b0 = sv[p]; a0 = p; }
            float b1 = sv[5];  int a1 = 5;
            #pragma unroll
            for (int p = 6; p < 10; p++)  if (sv[p] > b1) { b1 = sv[p]; a1 = p; }
            float b2 = sv[10]; int a2 = 10;
            #pragma unroll
            for (int p = 11; p < 15; p++) if (sv[p] > b2) { b2 = sv[p]; a2 = p; }
            float b3 = sv[15]; int a3 = 15;
            #pragma unroll
            for (int p = 16; p < 20; p++) if (sv[p] > b3) { b3 = sv[p]; a3 = p; }
            if (b1 > b0) { b0 = b1; a0 = a1; }
            if (b3 > b2) { b2 = b3; a2 = a3; }
            if (b2 > b0) { b0 = b2; a0 = a2; }
            fvn = b0 + ft;
            bp[s][n] = (unsigned char)a0;
        }
        __syncwarp();
        if (n < TT) fv[n] = fvn;
        __syncwarp();
    }

    // backwalk each end hypothesis (lane = end tag)
    if (n < TT) {
        int tag = n;
        for (int k = BSV - 1; k >= 0; k--) {
            g_pathtab[b][n][k] = (unsigned char)tag;
            tag = bp[k][tag];
        }
        g_entrytab[b][n] = (unsigned char)tag;
    }
}

// ---------------- kernel 4d: terminal + block backtrace + path emission ----------------
__global__ __launch_bounds__(1024) void vit_final_kernel(
    const float* __restrict__ trans, const int* __restrict__ stopp,
    float* __restrict__ out)
{
    __shared__ unsigned char entry_s[NB][TT];
    __shared__ unsigned char endtag[NB];
    const int tid = threadIdx.x;

    for (int x = tid; x < NB * TT; x += 1024)
        ((unsigned char*)entry_s)[x] = ((const unsigned char*)g_entrytab)[x];
    __syncthreads();

    if (tid == 0) {
        const int stop = *stopp;
        float best = g_fvs[NB][0] + trans[stop * TT + 0];
        int bt = 0;
        for (int p = 1; p < TT; p++) {
            float v = g_fvs[NB][p] + trans[stop * TT + p];
            if (v > best) { best = v; bt = p; }
        }
        out[0] = best;
        endtag[NB - 1] = (unsigned char)bt;
        for (int b = NB - 1; b >= 1; b--)
            endtag[b - 1] = entry_s[b][endtag[b]];
    }
    __syncthreads();

    for (int t = tid; t < SQ; t += 1024) {
        int b = t >> 5, k = t & 31;
        out[1 + t] = (float)g_pathtab[b][endtag[b]][k];
    }
}

// ---------------- launcher: overlapped (R12 topology) + scan viterbi ----------------
extern "C" void kernel_launch(void* const* d_in, const int* in_sizes, int n_in,
                              void* d_out, int out_size) {
    const int*   sent  = (const int*)  d_in[0];
    const float* embed = (const float*)d_in[1];
    const float* Wihf  = (const float*)d_in[2];
    const float* Whhf  = (const float*)d_in[3];
    const float* bf    = (const float*)d_in[4];
    const float* Wihb  = (const float*)d_in[5];
    const float* Whhb  = (const float*)d_in[6];
    const float* bb    = (const float*)d_in[7];
    const float* h0    = (const float*)d_in[8];
    const float* c0    = (const float*)d_in[9];
    const float* Wtag  = (const float*)d_in[10];
    const float* btag  = (const float*)d_in[11];
    const float* trans = (const float*)d_in[12];
    const int*   start = (const int*)  d_in[13];
    const int*   stop  = (const int*)  d_in[14];
    float* out = (float*)d_out;

    static cudaStream_t s_b = nullptr;
    static cudaEvent_t ev_fork = nullptr, ev_join = nullptr;
    if (s_b == nullptr) {
        int prio_lo = 0, prio_hi = 0;
        cudaDeviceGetStreamPriorityRange(&prio_lo, &prio_hi);
        cudaStreamCreateWithPriority(&s_b, cudaStreamNonBlocking, prio_lo);
        cudaEventCreateWithFlags(&ev_fork, cudaEventDisableTiming);
        cudaEventCreateWithFlags(&ev_join, cudaEventDisableTiming);
    }

    init_kernel<<<1, 1024>>>(h0);

    // fork: GEMM on low-priority side stream, LSTM on main stream
    cudaEventRecord(ev_fork, 0);
    cudaStreamWaitEvent(s_b, ev_fork, 0);
    gemm_pre_kernel<<<dim3(2, 16, 32), 256, 0, s_b>>>(sent, embed, Wihf, bf, Wihb, bb);
    lstm_kernel<<<128, 256>>>(Whhf, Whhb, c0);
    cudaEventRecord(ev_join, s_b);
    cudaStreamWaitEvent(0, ev_join, 0);

    dummy_kernel<<<1, 1>>>();
    feats_kernel<<<SQ / 8, 160>>>(Wtag, btag);

    // parallel max-plus-scan Viterbi
    vit_compose_kernel<<<NB, 400>>>(trans);
    vit_scan_kernel<<<1, 400>>>(start);
    vit_block_kernel<<<NB, 32>>>(trans);
    vit_final_kernel<<<1, 1024>>>(trans, stop, out);
}